// round 1
// baseline (speedup 1.0000x reference)
#include <cuda_runtime.h>
#include <float.h>

#define N_NODES 50000
#define N_EDGES 800000
#define IN_CH   128
#define HEADS   4
#define OUT_CH  32
#define FEAT    (HEADS*OUT_CH)   // 128
#define NEG_SLOPE 0.2f

// ---------------- scratch (static device globals: allocation-free) -----------
__device__ float g_feat[N_NODES * FEAT];   // transposed layout: [n][d][h] -> g_feat[n*128 + d*4 + h]
__device__ float g_el[N_NODES * HEADS];    // [n][h]
__device__ float g_er[N_NODES * HEADS];    // [n][h]
__device__ int   g_deg[N_NODES];
__device__ int   g_off[N_NODES + 1];
__device__ int   g_cur[N_NODES];
__device__ int   g_csr[N_EDGES];           // src indices grouped by dst

// ---------------- 1) feat = x @ W, fused el/er epilogue ----------------------
// block: 256 threads = 16 rows x 16 col-groups (8 cols each). K chunked by 64.
__global__ void gemm_feat_kernel(const float* __restrict__ x,
                                 const float* __restrict__ W,
                                 const float* __restrict__ attn_l,
                                 const float* __restrict__ attn_r) {
    __shared__ float Ws[64 * 128];   // 32 KB
    __shared__ float xs[16 * 64];    // 4 KB

    const int tid = threadIdx.x;
    const int rl  = tid >> 4;        // local row 0..15
    const int g   = tid & 15;        // col group 0..15 (cols g*8..g*8+7)
    const int row = blockIdx.x * 16 + rl;   // N divisible by 16: no guard needed

    float acc[8];
    #pragma unroll
    for (int j = 0; j < 8; j++) acc[j] = 0.0f;

    for (int kk = 0; kk < IN_CH; kk += 64) {
        // cooperative load of W[kk..kk+63][0..127]  (8192 floats)
        {
            const float4* Wg  = (const float4*)(W + kk * FEAT);
            float4*       Wsv = (float4*)Ws;
            #pragma unroll
            for (int i = 0; i < 8; i++)
                Wsv[tid + i * 256] = Wg[tid + i * 256];
        }
        // cooperative load of x tile [16][64]  (1 float4 per thread)
        {
            int r2 = tid >> 4, c4 = tid & 15;
            ((float4*)xs)[r2 * 16 + c4] =
                *(const float4*)(x + (blockIdx.x * 16 + r2) * IN_CH + kk + c4 * 4);
        }
        __syncthreads();

        const float4* Wv = (const float4*)Ws;
        #pragma unroll 8
        for (int k = 0; k < 64; k++) {
            float  xv = xs[rl * 64 + k];
            float4 a  = Wv[k * 32 + g * 2];
            float4 b  = Wv[k * 32 + g * 2 + 1];
            acc[0] += xv * a.x;  acc[1] += xv * a.y;
            acc[2] += xv * a.z;  acc[3] += xv * a.w;
            acc[4] += xv * b.x;  acc[5] += xv * b.y;
            acc[6] += xv * b.z;  acc[7] += xv * b.w;
        }
        __syncthreads();
    }

    // this thread's 8 cols live in one head: h = g/4, d = (g%4)*8 + j
    const int h     = g >> 2;
    const int dbase = (g & 3) * 8;

    // store feat transposed: [row][d][h]
    float* fr = g_feat + row * FEAT;
    #pragma unroll
    for (int j = 0; j < 8; j++) fr[(dbase + j) * HEADS + h] = acc[j];

    // attention partial dots
    float pl = 0.0f, pr = 0.0f;
    #pragma unroll
    for (int j = 0; j < 8; j++) {
        pl += acc[j] * __ldg(&attn_l[h * OUT_CH + dbase + j]);
        pr += acc[j] * __ldg(&attn_r[h * OUT_CH + dbase + j]);
    }
    // reduce across the 4 col-groups of this head (4 consecutive, 4-aligned lanes)
    pl += __shfl_down_sync(0xffffffffu, pl, 1, 4);
    pl += __shfl_down_sync(0xffffffffu, pl, 2, 4);
    pr += __shfl_down_sync(0xffffffffu, pr, 1, 4);
    pr += __shfl_down_sync(0xffffffffu, pr, 2, 4);
    if ((g & 3) == 0) {
        g_el[row * HEADS + h] = pl;
        g_er[row * HEADS + h] = pr;
    }
}

// ---------------- 2) CSR build ------------------------------------------------
__global__ void zero_deg_kernel() {
    int i = blockIdx.x * blockDim.x + threadIdx.x;
    if (i < N_NODES) g_deg[i] = 0;
}

__global__ void count_deg_kernel(const int* __restrict__ dst, int nE) {
    int i = blockIdx.x * blockDim.x + threadIdx.x;
    if (i < nE) atomicAdd(&g_deg[dst[i]], 1);
}

__global__ void scan_kernel(int nE) {
    __shared__ int sm[1024];
    const int t  = threadIdx.x;
    const int CH = (N_NODES + 1023) / 1024;  // 49
    const int base = t * CH;

    int sum = 0;
    for (int i = 0; i < CH; i++) {
        int idx = base + i;
        if (idx < N_NODES) sum += g_deg[idx];
    }
    sm[t] = sum;
    __syncthreads();
    // inclusive Hillis-Steele scan over 1024 partials
    for (int st = 1; st < 1024; st <<= 1) {
        int v = (t >= st) ? sm[t - st] : 0;
        __syncthreads();
        sm[t] += v;
        __syncthreads();
    }
    int run = (t == 0) ? 0 : sm[t - 1];
    for (int i = 0; i < CH; i++) {
        int idx = base + i;
        if (idx < N_NODES) {
            g_off[idx] = run;
            g_cur[idx] = run;
            run += g_deg[idx];
        }
    }
    if (t == 0) g_off[N_NODES] = nE;
}

__global__ void scatter_kernel(const int* __restrict__ src,
                               const int* __restrict__ dst, int nE) {
    int i = blockIdx.x * blockDim.x + threadIdx.x;
    if (i < nE) {
        int p = atomicAdd(&g_cur[dst[i]], 1);
        g_csr[p] = src[i];
    }
}

// ---------------- 3) fused online-softmax aggregation (1 warp / dst node) ----
__global__ void aggregate_kernel(const float* __restrict__ bias,
                                 float* __restrict__ out) {
    const int warp = (blockIdx.x * blockDim.x + threadIdx.x) >> 5;
    const int lane = threadIdx.x & 31;
    if (warp >= N_NODES) return;

    const int beg = g_off[warp];
    const int end = g_off[warp + 1];

    float er4[HEADS];
    {
        float4 e = *(const float4*)&g_er[warp * HEADS];
        er4[0] = e.x; er4[1] = e.y; er4[2] = e.z; er4[3] = e.w;
    }

    float m[HEADS], s[HEADS], acc[HEADS];
    #pragma unroll
    for (int h = 0; h < HEADS; h++) { m[h] = -FLT_MAX; s[h] = 0.0f; acc[h] = 0.0f; }

    for (int i = beg; i < end; i++) {
        const int src = __ldg(&g_csr[i]);

        float el4[HEADS];
        {
            float4 e = *(const float4*)&g_el[src * HEADS];
            el4[0] = e.x; el4[1] = e.y; el4[2] = e.z; el4[3] = e.w;
        }
        // feature gather: all 4 heads for this lane's feature dim in one float4
        float4 f = *(const float4*)&g_feat[src * FEAT + lane * HEADS];
        float fv[HEADS] = { f.x, f.y, f.z, f.w };

        #pragma unroll
        for (int h = 0; h < HEADS; h++) {
            float e = el4[h] + er4[h];
            e = (e > 0.0f) ? e : NEG_SLOPE * e;  // leaky relu
            float w;
            if (e > m[h]) {
                float c = __expf(m[h] - e);      // first edge: exp(-inf)=0, zeroes nothing
                s[h]   *= c;
                acc[h] *= c;
                m[h]    = e;
                w       = 1.0f;
            } else {
                w = __expf(e - m[h]);
            }
            s[h]   += w;
            acc[h] += w * fv[h];
        }
    }

    float o = 0.0f;
    const bool has_edges = (end > beg);
    #pragma unroll
    for (int h = 0; h < HEADS; h++) {
        float a = has_edges ? (acc[h] / s[h]) : 0.0f;
        o += a + __ldg(&bias[h * OUT_CH + lane]);
    }
    out[warp * OUT_CH + lane] = o * (1.0f / HEADS);
}

// ---------------- launch ------------------------------------------------------
extern "C" void kernel_launch(void* const* d_in, const int* in_sizes, int n_in,
                              void* d_out, int out_size) {
    const float* x      = (const float*)d_in[0];
    const int*   src    = (const int*)  d_in[1];
    const int*   dst    = (const int*)  d_in[2];
    const float* W      = (const float*)d_in[3];
    const float* attn_l = (const float*)d_in[4];
    const float* attn_r = (const float*)d_in[5];
    const float* bias   = (const float*)d_in[6];
    float*       out    = (float*)d_out;

    const int nE = in_sizes[1];

    gemm_feat_kernel<<<N_NODES / 16, 256>>>(x, W, attn_l, attn_r);

    zero_deg_kernel<<<(N_NODES + 255) / 256, 256>>>();
    count_deg_kernel<<<(nE + 255) / 256, 256>>>(dst, nE);
    scan_kernel<<<1, 1024>>>(nE);
    scatter_kernel<<<(nE + 255) / 256, 256>>>(src, dst, nE);

    // 8 warps per block, 1 warp per dst node
    aggregate_kernel<<<(N_NODES + 7) / 8, 256>>>(bias, out);
}

// round 2
// speedup vs baseline: 3.5318x; 3.5318x over previous
#include <cuda_runtime.h>

#define N_NODES 50000
#define N_PAD   50176            // 49 * 1024
#define IN_CH   128
#define HEADS   4
#define OUT_CH  32
#define FEAT    128
#define NEG_SLOPE 0.2f
#define SCAN_NB 49
#define MAX_E   800000

// ---------------- scratch (static device globals: allocation-free) -----------
__device__ __align__(16) float g_feat[N_NODES * FEAT];  // [n][h*32+d] natural layout
__device__ __align__(16) float g_el[N_NODES * HEADS];
__device__ __align__(16) float g_er[N_NODES * HEADS];
__device__ __align__(16) int   g_deg[N_PAD];
__device__ __align__(16) int   g_off[N_PAD + 16];
__device__ __align__(16) int   g_cur[N_PAD];
__device__ int g_bsum[SCAN_NB];
__device__ int g_boff[64];
__device__ __align__(16) int   g_csr[MAX_E];
__device__ __align__(16) float g_w[MAX_E * 4];          // per-edge per-head exp weights

// ---------------- 1) feat = x @ W  (64x128 tile, 8x4 per-thread) -------------
__global__ __launch_bounds__(256) void gemm_kernel(const float* __restrict__ x,
                                                   const float* __restrict__ W) {
    __shared__ __align__(16) float Ws[32 * 128];  // [k][n], 16 KB
    __shared__ float xs[64 * 33];                 // [m][k] pad 33, 8.25 KB

    const int t  = threadIdx.x;
    const int tx = t & 15;       // col group
    const int ty = t >> 4;       // row group
    const int rbase = blockIdx.x * 64;

    float4 accA[4], accB[4];
    #pragma unroll
    for (int i = 0; i < 4; i++) {
        accA[i] = make_float4(0.f, 0.f, 0.f, 0.f);
        accB[i] = make_float4(0.f, 0.f, 0.f, 0.f);
    }

    for (int kk = 0; kk < IN_CH; kk += 32) {
        // W chunk [32][128] -> Ws (coalesced float4)
        {
            const float4* Wg  = (const float4*)(W + kk * FEAT);
            float4*       Wsv = (float4*)Ws;
            #pragma unroll
            for (int p = 0; p < 4; p++) Wsv[p * 256 + t] = Wg[p * 256 + t];
        }
        // x chunk [64][32] -> xs (row-guarded)
        #pragma unroll
        for (int p = 0; p < 2; p++) {
            int v = p * 256 + t;
            int r = v >> 3, c4 = v & 7;
            int row = rbase + r;
            float4 xv = make_float4(0.f, 0.f, 0.f, 0.f);
            if (row < N_NODES) xv = *(const float4*)(x + row * IN_CH + kk + c4 * 4);
            float* d = xs + r * 33 + c4 * 4;
            d[0] = xv.x; d[1] = xv.y; d[2] = xv.z; d[3] = xv.w;
        }
        __syncthreads();

        const float4* Wv = (const float4*)Ws;
        #pragma unroll 8
        for (int k = 0; k < 32; k++) {
            float4 wa = Wv[k * 32 + tx];
            float4 wb = Wv[k * 32 + 16 + tx];
            #pragma unroll
            for (int i = 0; i < 4; i++) {
                float xv = xs[(ty * 4 + i) * 33 + k];
                accA[i].x += xv * wa.x; accA[i].y += xv * wa.y;
                accA[i].z += xv * wa.z; accA[i].w += xv * wa.w;
                accB[i].x += xv * wb.x; accB[i].y += xv * wb.y;
                accB[i].z += xv * wb.z; accB[i].w += xv * wb.w;
            }
        }
        __syncthreads();
    }

    #pragma unroll
    for (int i = 0; i < 4; i++) {
        int row = rbase + ty * 4 + i;
        if (row < N_NODES) {
            *(float4*)(g_feat + row * FEAT + tx * 4)      = accA[i];
            *(float4*)(g_feat + row * FEAT + 64 + tx * 4) = accB[i];
        }
    }
}

// ---------------- 2) el/er = feat . attn  (1 warp / node) --------------------
__global__ __launch_bounds__(256) void elr_kernel(const float* __restrict__ attn_l,
                                                  const float* __restrict__ attn_r) {
    int node = (blockIdx.x * blockDim.x + threadIdx.x) >> 5;
    int lane = threadIdx.x & 31;
    if (node >= N_NODES) return;

    float4 f = *(const float4*)(g_feat + node * FEAT + lane * 4);
    int h  = lane >> 3;
    int db = (lane & 7) * 4;
    float4 al = *(const float4*)(attn_l + h * OUT_CH + db);
    float4 ar = *(const float4*)(attn_r + h * OUT_CH + db);
    float pl = f.x * al.x + f.y * al.y + f.z * al.z + f.w * al.w;
    float pr = f.x * ar.x + f.y * ar.y + f.z * ar.z + f.w * ar.w;
    #pragma unroll
    for (int d = 4; d; d >>= 1) {
        pl += __shfl_down_sync(0xffffffffu, pl, d, 8);
        pr += __shfl_down_sync(0xffffffffu, pr, d, 8);
    }
    if ((lane & 7) == 0) {
        g_el[node * HEADS + h] = pl;
        g_er[node * HEADS + h] = pr;
    }
}

// ---------------- 3) CSR build ------------------------------------------------
__global__ void zero_deg_kernel() {
    int i = blockIdx.x * blockDim.x + threadIdx.x;
    if (i < N_PAD) g_deg[i] = 0;
}

__global__ void count_kernel(const int* __restrict__ dst, int nE) {
    int i4 = (blockIdx.x * blockDim.x + threadIdx.x) * 4;
    if (i4 + 3 < nE) {
        int4 d = *(const int4*)(dst + i4);
        atomicAdd(&g_deg[d.x], 1); atomicAdd(&g_deg[d.y], 1);
        atomicAdd(&g_deg[d.z], 1); atomicAdd(&g_deg[d.w], 1);
    } else {
        for (int i = i4; i < nE; i++) atomicAdd(&g_deg[dst[i]], 1);
    }
}

__global__ __launch_bounds__(256) void scan_p1() {
    int t = threadIdx.x, b = blockIdx.x;
    int4 v = *(const int4*)(g_deg + b * 1024 + t * 4);
    int sum = v.x + v.y + v.z + v.w;
    #pragma unroll
    for (int d = 16; d; d >>= 1) sum += __shfl_xor_sync(0xffffffffu, sum, d);
    __shared__ int wsum[8];
    if ((t & 31) == 0) wsum[t >> 5] = sum;
    __syncthreads();
    if (t < 8) {
        int xv = wsum[t];
        #pragma unroll
        for (int d = 4; d; d >>= 1) xv += __shfl_xor_sync(0xffu, xv, d, 8);
        if (t == 0) g_bsum[b] = xv;
    }
}

__global__ void scan_p2() {
    int t = threadIdx.x;  // 64 threads
    int v = (t < SCAN_NB) ? g_bsum[t] : 0;
    int inc = v;
    #pragma unroll
    for (int d = 1; d < 32; d <<= 1) {
        int u = __shfl_up_sync(0xffffffffu, inc, d);
        if ((t & 31) >= d) inc += u;
    }
    __shared__ int w0;
    if (t == 31) w0 = inc;
    __syncthreads();
    if (t >= 32) inc += w0;
    if (t < SCAN_NB) g_boff[t] = inc - v;
}

__global__ __launch_bounds__(256) void scan_p3() {
    int t = threadIdx.x, b = blockIdx.x;
    int base = b * 1024 + t * 4;
    int4 v = *(const int4*)(g_deg + base);
    int tsum = v.x + v.y + v.z + v.w;
    int lane = t & 31, wid = t >> 5;
    int inc = tsum;
    #pragma unroll
    for (int d = 1; d < 32; d <<= 1) {
        int u = __shfl_up_sync(0xffffffffu, inc, d);
        if (lane >= d) inc += u;
    }
    __shared__ int wtot[8], woff[8];
    if (lane == 31) wtot[wid] = inc;
    __syncthreads();
    if (t < 8) {
        int xv = wtot[t], p = xv;
        #pragma unroll
        for (int d = 1; d < 8; d <<= 1) {
            int u = __shfl_up_sync(0xffu, p, d, 8);
            if (t >= d) p += u;
        }
        woff[t] = p - xv;
    }
    __syncthreads();
    int pref = g_boff[b] + woff[wid] + (inc - tsum);
    int4 o;
    o.x = pref;
    o.y = o.x + v.x;
    o.z = o.y + v.y;
    o.w = o.z + v.z;
    *(int4*)(g_off + base) = o;
    *(int4*)(g_cur + base) = o;
}

// ---------------- 4) scatter + edge weights ----------------------------------
__device__ __forceinline__ float lrelu_exp(float e) {
    e = e > 0.f ? e : NEG_SLOPE * e;
    return __expf(e);
}

__global__ void scatter_kernel(const int* __restrict__ src,
                               const int* __restrict__ dst, int nE) {
    int i = blockIdx.x * blockDim.x + threadIdx.x;
    if (i >= nE) return;
    int s = src[i], d = dst[i];
    float4 a = *(const float4*)(g_el + s * 4);
    float4 b = *(const float4*)(g_er + d * 4);
    float4 w;
    w.x = lrelu_exp(a.x + b.x);
    w.y = lrelu_exp(a.y + b.y);
    w.z = lrelu_exp(a.z + b.z);
    w.w = lrelu_exp(a.w + b.w);
    int p = atomicAdd(&g_cur[d], 1);
    g_csr[p] = s;
    *(float4*)(g_w + (size_t)p * 4) = w;
}

// ---------------- 5) aggregation (1 warp / dst node, branch-free loop) -------
__global__ __launch_bounds__(256) void aggregate_kernel(const float* __restrict__ bias,
                                                        float* __restrict__ out) {
    int node = (blockIdx.x * blockDim.x + threadIdx.x) >> 5;
    int lane = threadIdx.x & 31;
    if (node >= N_NODES) return;

    int beg = g_off[node], end = g_off[node + 1];
    int hh = lane >> 3;                        // this lane's head

    float4 acc = make_float4(0.f, 0.f, 0.f, 0.f);
    float s = 0.f;
    for (int i = beg; i < end; i++) {
        int sp   = __ldg(&g_csr[i]);                         // uniform
        float wv = __ldg(&g_w[i * 4 + hh]);                  // broadcast per head
        float4 f = *(const float4*)(g_feat + sp * FEAT + lane * 4);
        acc.x += wv * f.x; acc.y += wv * f.y;
        acc.z += wv * f.z; acc.w += wv * f.w;
        s += wv;
    }

    float inv = (end > beg) ? (1.0f / s) : 0.0f;
    float4 bv = *(const float4*)(bias + hh * OUT_CH + (lane & 7) * 4);
    acc.x = acc.x * inv + bv.x;
    acc.y = acc.y * inv + bv.y;
    acc.z = acc.z * inv + bv.z;
    acc.w = acc.w * inv + bv.w;

    // combine 4 heads: lanes l, l^8, l^16, l^24 hold the same output dims
    #pragma unroll
    for (int d = 8; d < 32; d <<= 1) {
        acc.x += __shfl_xor_sync(0xffffffffu, acc.x, d);
        acc.y += __shfl_xor_sync(0xffffffffu, acc.y, d);
        acc.z += __shfl_xor_sync(0xffffffffu, acc.z, d);
        acc.w += __shfl_xor_sync(0xffffffffu, acc.w, d);
    }
    if (lane < 8) {
        acc.x *= 0.25f; acc.y *= 0.25f; acc.z *= 0.25f; acc.w *= 0.25f;
        *(float4*)(out + node * OUT_CH + lane * 4) = acc;
    }
}

// ---------------- launch ------------------------------------------------------
extern "C" void kernel_launch(void* const* d_in, const int* in_sizes, int n_in,
                              void* d_out, int out_size) {
    const float* x      = (const float*)d_in[0];
    const int*   src    = (const int*)  d_in[1];
    const int*   dst    = (const int*)  d_in[2];
    const float* W      = (const float*)d_in[3];
    const float* attn_l = (const float*)d_in[4];
    const float* attn_r = (const float*)d_in[5];
    const float* bias   = (const float*)d_in[6];
    float*       out    = (float*)d_out;

    const int nE = in_sizes[1];

    // CSR build (independent of gemm)
    zero_deg_kernel<<<(N_PAD + 255) / 256, 256>>>();
    count_kernel<<<((nE + 3) / 4 + 255) / 256, 256>>>(dst, nE);
    scan_p1<<<SCAN_NB, 256>>>();
    scan_p2<<<1, 64>>>();
    scan_p3<<<SCAN_NB, 256>>>();

    // projection + attention terms
    gemm_kernel<<<(N_NODES + 63) / 64, 256>>>(x, W);
    elr_kernel<<<(N_NODES * 32 + 255) / 256, 256>>>(attn_l, attn_r);

    // edge weights + CSR scatter
    scatter_kernel<<<(nE + 255) / 256, 256>>>(src, dst, nE);

    // fused softmax-normalize + aggregate + head mean
    aggregate_kernel<<<(N_NODES * 32 + 255) / 256, 256>>>(bias, out);
}

// round 3
// speedup vs baseline: 3.9064x; 1.1061x over previous
#include <cuda_runtime.h>
#include <cuda_fp16.h>

#define N_NODES 50000
#define N_PAD   50176            // 49 * 1024
#define IN_CH   128
#define HEADS   4
#define OUT_CH  32
#define FEAT    128
#define NEG_SLOPE 0.2f
#define SCAN_NB 49
#define MAX_E   800000

// ---------------- scratch (static device globals: allocation-free) -----------
__device__ __align__(16) __half g_feat_h[N_NODES * FEAT];  // fp16 features [n][h*32+d]
__device__ __align__(16) float  g_el[N_NODES * HEADS];
__device__ __align__(16) float  g_er[N_NODES * HEADS];
__device__ __align__(16) int    g_deg[N_PAD];
__device__ __align__(16) int    g_off[N_PAD + 16];
__device__ __align__(16) int    g_cur[N_PAD];
__device__ int g_bsum[SCAN_NB];
__device__ __align__(16) int    g_csr[MAX_E];
__device__ __align__(16) float  g_w[MAX_E * 4];            // per-edge per-head exp weights

// ---------------- 1) feat = x @ W  + fused el/er epilogue --------------------
// 64x128 tile, 128 threads, 8 rows x 8 cols per thread (split 4+4 across halves)
__global__ __launch_bounds__(128) void gemm_kernel(const float* __restrict__ x,
                                                   const float* __restrict__ W,
                                                   const float* __restrict__ attn_l,
                                                   const float* __restrict__ attn_r) {
    __shared__ __align__(16) float Ws[32 * 128];   // [k][n], 16 KB
    __shared__ float xs[64 * 33];                  // [m][k] pad, 8.5 KB

    const int t  = threadIdx.x;
    const int tx = t & 15;          // col group: cols tx*4 (A) and 64+tx*4 (B)
    const int ty = t >> 4;          // row group: rows ty*8 .. ty*8+7
    const int rbase = blockIdx.x * 64;

    float4 accA[8], accB[8];
    #pragma unroll
    for (int i = 0; i < 8; i++) {
        accA[i] = make_float4(0.f, 0.f, 0.f, 0.f);
        accB[i] = make_float4(0.f, 0.f, 0.f, 0.f);
    }

    for (int kk = 0; kk < IN_CH; kk += 32) {
        // W chunk [32][128] -> Ws  (1024 float4 / 128 thr = 8 each, coalesced)
        {
            const float4* Wg  = (const float4*)(W + kk * FEAT);
            float4*       Wsv = (float4*)Ws;
            #pragma unroll
            for (int p = 0; p < 8; p++) Wsv[p * 128 + t] = Wg[p * 128 + t];
        }
        // x chunk [64][32] -> xs  (512 float4 / 128 thr = 4 each, row-guarded)
        #pragma unroll
        for (int p = 0; p < 4; p++) {
            int idx = p * 128 + t;
            int r = idx >> 3, k4 = idx & 7;
            int row = rbase + r;
            float4 xv = make_float4(0.f, 0.f, 0.f, 0.f);
            if (row < N_NODES) xv = *(const float4*)(x + row * IN_CH + kk + k4 * 4);
            float* d = xs + r * 33 + k4 * 4;
            d[0] = xv.x; d[1] = xv.y; d[2] = xv.z; d[3] = xv.w;
        }
        __syncthreads();

        const float4* Wv = (const float4*)Ws;
        #pragma unroll 4
        for (int k = 0; k < 32; k++) {
            float4 wa = Wv[k * 32 + tx];
            float4 wb = Wv[k * 32 + 16 + tx];
            #pragma unroll
            for (int i = 0; i < 8; i++) {
                float xv = xs[(ty * 8 + i) * 33 + k];
                accA[i].x += xv * wa.x; accA[i].y += xv * wa.y;
                accA[i].z += xv * wa.z; accA[i].w += xv * wa.w;
                accB[i].x += xv * wb.x; accB[i].y += xv * wb.y;
                accB[i].z += xv * wb.z; accB[i].w += xv * wb.w;
            }
        }
        __syncthreads();
    }

    // heads: A cols = tx*4 (head tx>>3), B cols = 64+tx*4 (head 2+(tx>>3))
    const int hA = tx >> 3;
    const int hB = 2 + hA;
    const int db = (tx & 7) * 4;
    float4 alA = *(const float4*)(attn_l + hA * OUT_CH + db);
    float4 arA = *(const float4*)(attn_r + hA * OUT_CH + db);
    float4 alB = *(const float4*)(attn_l + hB * OUT_CH + db);
    float4 arB = *(const float4*)(attn_r + hB * OUT_CH + db);

    #pragma unroll
    for (int i = 0; i < 8; i++) {
        int row = rbase + ty * 8 + i;

        // fused el/er dot products, reduced over the 8 tx-lanes of each head
        float plA = accA[i].x*alA.x + accA[i].y*alA.y + accA[i].z*alA.z + accA[i].w*alA.w;
        float prA = accA[i].x*arA.x + accA[i].y*arA.y + accA[i].z*arA.z + accA[i].w*arA.w;
        float plB = accB[i].x*alB.x + accB[i].y*alB.y + accB[i].z*alB.z + accB[i].w*alB.w;
        float prB = accB[i].x*arB.x + accB[i].y*arB.y + accB[i].z*arB.z + accB[i].w*arB.w;
        #pragma unroll
        for (int d = 4; d; d >>= 1) {
            plA += __shfl_down_sync(0xffffffffu, plA, d, 8);
            prA += __shfl_down_sync(0xffffffffu, prA, d, 8);
            plB += __shfl_down_sync(0xffffffffu, plB, d, 8);
            prB += __shfl_down_sync(0xffffffffu, prB, d, 8);
        }

        if (row < N_NODES) {
            if ((tx & 7) == 0) {
                g_el[row * HEADS + hA] = plA;
                g_er[row * HEADS + hA] = prA;
                g_el[row * HEADS + hB] = plB;
                g_er[row * HEADS + hB] = prB;
            }
            // fp16 feature store
            __half2 a0 = __floats2half2_rn(accA[i].x, accA[i].y);
            __half2 a1 = __floats2half2_rn(accA[i].z, accA[i].w);
            __half2 b0 = __floats2half2_rn(accB[i].x, accB[i].y);
            __half2 b1 = __floats2half2_rn(accB[i].z, accB[i].w);
            __half* fr = g_feat_h + row * FEAT;
            *(__half2*)(fr + tx * 4)          = a0;
            *(__half2*)(fr + tx * 4 + 2)      = a1;
            *(__half2*)(fr + 64 + tx * 4)     = b0;
            *(__half2*)(fr + 64 + tx * 4 + 2) = b1;
        }
    }
}

// ---------------- 2) CSR build ------------------------------------------------
__global__ void zero_deg_kernel() {
    int i = blockIdx.x * blockDim.x + threadIdx.x;
    if (i < N_PAD) g_deg[i] = 0;
}

__global__ void count_kernel(const int* __restrict__ dst, int nE) {
    int i4 = (blockIdx.x * blockDim.x + threadIdx.x) * 4;
    if (i4 + 3 < nE) {
        int4 d = *(const int4*)(dst + i4);
        atomicAdd(&g_deg[d.x], 1); atomicAdd(&g_deg[d.y], 1);
        atomicAdd(&g_deg[d.z], 1); atomicAdd(&g_deg[d.w], 1);
    } else {
        for (int i = i4; i < nE; i++) atomicAdd(&g_deg[dst[i]], 1);
    }
}

__global__ __launch_bounds__(256) void scan_p1() {
    int t = threadIdx.x, b = blockIdx.x;
    int4 v = *(const int4*)(g_deg + b * 1024 + t * 4);
    int sum = v.x + v.y + v.z + v.w;
    #pragma unroll
    for (int d = 16; d; d >>= 1) sum += __shfl_xor_sync(0xffffffffu, sum, d);
    __shared__ int wsum[8];
    if ((t & 31) == 0) wsum[t >> 5] = sum;
    __syncthreads();
    if (t < 8) {
        int xv = wsum[t];
        #pragma unroll
        for (int d = 4; d; d >>= 1) xv += __shfl_xor_sync(0xffu, xv, d, 8);
        if (t == 0) g_bsum[b] = xv;
    }
}

// scan_p3 with inlined block-offset computation (scan_p2 eliminated)
__global__ __launch_bounds__(256) void scan_p3() {
    int t = threadIdx.x, b = blockIdx.x;
    __shared__ int s_part[2];

    if (t < 64) {
        int v = (t < SCAN_NB && t < b) ? g_bsum[t] : 0;
        #pragma unroll
        for (int d = 16; d; d >>= 1) v += __shfl_xor_sync(0xffffffffu, v, d);
        if ((t & 31) == 0) s_part[t >> 5] = v;
    }
    __syncthreads();
    const int boff = s_part[0] + s_part[1];

    int base = b * 1024 + t * 4;
    int4 v = *(const int4*)(g_deg + base);
    int tsum = v.x + v.y + v.z + v.w;
    int lane = t & 31, wid = t >> 5;
    int inc = tsum;
    #pragma unroll
    for (int d = 1; d < 32; d <<= 1) {
        int u = __shfl_up_sync(0xffffffffu, inc, d);
        if (lane >= d) inc += u;
    }
    __shared__ int wtot[8], woff[8];
    if (lane == 31) wtot[wid] = inc;
    __syncthreads();
    if (t < 8) {
        int xv = wtot[t], p = xv;
        #pragma unroll
        for (int d = 1; d < 8; d <<= 1) {
            int u = __shfl_up_sync(0xffu, p, d, 8);
            if (t >= d) p += u;
        }
        woff[t] = p - xv;
    }
    __syncthreads();
    int pref = boff + woff[wid] + (inc - tsum);
    int4 o;
    o.x = pref;
    o.y = o.x + v.x;
    o.z = o.y + v.y;
    o.w = o.z + v.z;
    *(int4*)(g_off + base) = o;
    *(int4*)(g_cur + base) = o;
}

// ---------------- 3) scatter + edge weights ----------------------------------
__device__ __forceinline__ float lrelu_exp(float e) {
    e = e > 0.f ? e : NEG_SLOPE * e;
    return __expf(e);
}

__global__ void scatter_kernel(const int* __restrict__ src,
                               const int* __restrict__ dst, int nE) {
    int i = blockIdx.x * blockDim.x + threadIdx.x;
    if (i >= nE) return;
    int s = src[i], d = dst[i];
    float4 a = *(const float4*)(g_el + s * 4);
    float4 b = *(const float4*)(g_er + d * 4);
    float4 w;
    w.x = lrelu_exp(a.x + b.x);
    w.y = lrelu_exp(a.y + b.y);
    w.z = lrelu_exp(a.z + b.z);
    w.w = lrelu_exp(a.w + b.w);
    int p = atomicAdd(&g_cur[d], 1);
    g_csr[p] = s;
    *(float4*)(g_w + (size_t)p * 4) = w;
}

// ---------------- 4) aggregation (1 warp / dst node, fp16 gathers) -----------
__global__ __launch_bounds__(256) void aggregate_kernel(const float* __restrict__ bias,
                                                        float* __restrict__ out) {
    int node = (blockIdx.x * blockDim.x + threadIdx.x) >> 5;
    int lane = threadIdx.x & 31;
    if (node >= N_NODES) return;

    int beg = g_off[node], end = g_off[node + 1];
    int hh = lane >> 3;                        // this lane's head

    float4 acc = make_float4(0.f, 0.f, 0.f, 0.f);
    float s = 0.f;
    for (int i = beg; i < end; i++) {
        int sp   = __ldg(&g_csr[i]);                          // uniform
        float wv = __ldg(&g_w[i * 4 + hh]);                   // one sector / warp
        const __half2* fp = (const __half2*)(g_feat_h + sp * FEAT + lane * 4);
        float2 f0 = __half22float2(fp[0]);
        float2 f1 = __half22float2(fp[1]);
        acc.x += wv * f0.x; acc.y += wv * f0.y;
        acc.z += wv * f1.x; acc.w += wv * f1.y;
        s += wv;
    }

    float inv = (end > beg) ? (1.0f / s) : 0.0f;
    float4 bv = *(const float4*)(bias + hh * OUT_CH + (lane & 7) * 4);
    acc.x = acc.x * inv + bv.x;
    acc.y = acc.y * inv + bv.y;
    acc.z = acc.z * inv + bv.z;
    acc.w = acc.w * inv + bv.w;

    // combine 4 heads: lanes l, l^8, l^16, l^24 hold the same output dims
    #pragma unroll
    for (int d = 8; d < 32; d <<= 1) {
        acc.x += __shfl_xor_sync(0xffffffffu, acc.x, d);
        acc.y += __shfl_xor_sync(0xffffffffu, acc.y, d);
        acc.z += __shfl_xor_sync(0xffffffffu, acc.z, d);
        acc.w += __shfl_xor_sync(0xffffffffu, acc.w, d);
    }
    if (lane < 8) {
        acc.x *= 0.25f; acc.y *= 0.25f; acc.z *= 0.25f; acc.w *= 0.25f;
        *(float4*)(out + node * OUT_CH + lane * 4) = acc;
    }
}

// ---------------- launch ------------------------------------------------------
extern "C" void kernel_launch(void* const* d_in, const int* in_sizes, int n_in,
                              void* d_out, int out_size) {
    const float* x      = (const float*)d_in[0];
    const int*   src    = (const int*)  d_in[1];
    const int*   dst    = (const int*)  d_in[2];
    const float* W      = (const float*)d_in[3];
    const float* attn_l = (const float*)d_in[4];
    const float* attn_r = (const float*)d_in[5];
    const float* bias   = (const float*)d_in[6];
    float*       out    = (float*)d_out;

    const int nE = in_sizes[1];

    // CSR build
    zero_deg_kernel<<<(N_PAD + 255) / 256, 256>>>();
    count_kernel<<<((nE + 3) / 4 + 255) / 256, 256>>>(dst, nE);
    scan_p1<<<SCAN_NB, 256>>>();
    scan_p3<<<SCAN_NB, 256>>>();

    // projection + fused attention terms + fp16 feature store
    gemm_kernel<<<(N_NODES + 63) / 64, 128>>>(x, W, attn_l, attn_r);

    // edge weights + CSR scatter
    scatter_kernel<<<(nE + 255) / 256, 256>>>(src, dst, nE);

    // fused softmax-normalize + aggregate + head mean
    aggregate_kernel<<<(N_NODES * 32 + 255) / 256, 256>>>(bias, out);
}

// round 4
// speedup vs baseline: 4.7428x; 1.2141x over previous
#include <cuda_runtime.h>
#include <cuda_fp16.h>

#define N_NODES 50000
#define N_PAD   50176            // 49 * 1024
#define IN_CH   128
#define HEADS   4
#define OUT_CH  32
#define FEAT    128
#define NEG_SLOPE 0.2f
#define SCAN_NB 49
#define MAX_E   800000

// ---------------- scratch (static device globals: allocation-free) -----------
__device__ __align__(16) __half g_feat_h[N_NODES * FEAT];  // fp16 features [n][h*32+d]
__device__ __align__(16) float  g_el[N_NODES * HEADS];
__device__ __align__(16) float  g_er[N_NODES * HEADS];
__device__ __align__(16) int    g_deg[N_PAD];
__device__ __align__(16) int    g_off[N_PAD + 16];
__device__ __align__(16) int    g_cur[N_PAD];
__device__ int g_bsum[SCAN_NB];
__device__ __align__(16) int    g_csr[MAX_E];
__device__ __align__(16) float  g_w[MAX_E * 4];            // per-edge per-head exp weights

__device__ __forceinline__ unsigned f2tf32(float f) {
    unsigned o;
    asm("cvt.rna.tf32.f32 %0, %1;" : "=r"(o) : "f"(f));
    return o;
}

// ---------------- 1) feat = x @ W via tf32 mma + fused el/er epilogue --------
// 128x128 tile per block, 256 threads = 8 warps (4 M x 2 N).
// Warp tile: 32 rows x 64 cols (= 2 complete heads). K chunked by 32.
#define XS_STRIDE 36    // bank = (4g + c) % 32 : conflict-free A loads
#define WS_STRIDE 136   // bank = (8c + g) % 32 : conflict-free B loads

__global__ __launch_bounds__(256) void gemm_kernel(const float* __restrict__ x,
                                                   const float* __restrict__ W,
                                                   const float* __restrict__ attn_l,
                                                   const float* __restrict__ attn_r) {
    __shared__ unsigned xs[128 * XS_STRIDE];   // 18 KB, tf32 bits [m][k]
    __shared__ unsigned ws[32 * WS_STRIDE];    // 17 KB, tf32 bits [k][n]
    __shared__ float    s_attn[256];           // attn_l (0..127), attn_r (128..255)

    const int t      = threadIdx.x;
    const int lane   = t & 31;
    const int wid    = t >> 5;
    const int warp_m = wid & 3;               // 0..3 -> rows warp_m*32
    const int warp_n = wid >> 2;              // 0..1 -> cols warp_n*64
    const int g      = lane >> 2;             // group id 0..7
    const int c      = lane & 3;              // thread-in-group 0..3
    const int rbase  = blockIdx.x * 128;

    s_attn[t] = (t < 128) ? attn_l[t] : attn_r[t - 128];

    float d[2][8][4];                          // [mt][nt][frag]
    #pragma unroll
    for (int mt = 0; mt < 2; mt++)
        #pragma unroll
        for (int nt = 0; nt < 8; nt++)
            #pragma unroll
            for (int q = 0; q < 4; q++) d[mt][nt][q] = 0.f;

    for (int kk = 0; kk < IN_CH; kk += 32) {
        // load x chunk [128][32] -> xs (tf32), row-guarded
        #pragma unroll
        for (int p = 0; p < 4; p++) {
            int idx = p * 256 + t;
            int r = idx >> 3, c4 = idx & 7;
            int row = rbase + r;
            float4 xv = make_float4(0.f, 0.f, 0.f, 0.f);
            if (row < N_NODES) xv = *(const float4*)(x + row * IN_CH + kk + c4 * 4);
            unsigned* dptr = xs + r * XS_STRIDE + c4 * 4;
            dptr[0] = f2tf32(xv.x); dptr[1] = f2tf32(xv.y);
            dptr[2] = f2tf32(xv.z); dptr[3] = f2tf32(xv.w);
        }
        // load W chunk [32][128] -> ws (tf32)
        #pragma unroll
        for (int p = 0; p < 4; p++) {
            int idx = p * 256 + t;
            int k = idx >> 5, n4 = idx & 31;
            float4 wv = *(const float4*)(W + (kk + k) * FEAT + n4 * 4);
            unsigned* dptr = ws + k * WS_STRIDE + n4 * 4;
            dptr[0] = f2tf32(wv.x); dptr[1] = f2tf32(wv.y);
            dptr[2] = f2tf32(wv.z); dptr[3] = f2tf32(wv.w);
        }
        __syncthreads();

        #pragma unroll
        for (int k0 = 0; k0 < 32; k0 += 8) {
            // A fragments for both m-tiles
            unsigned a[2][4];
            #pragma unroll
            for (int mt = 0; mt < 2; mt++) {
                int r0 = (warp_m * 32 + mt * 16 + g) * XS_STRIDE + k0 + c;
                int r1 = r0 + 8 * XS_STRIDE;
                a[mt][0] = xs[r0];     a[mt][1] = xs[r1];
                a[mt][2] = xs[r0 + 4]; a[mt][3] = xs[r1 + 4];
            }
            #pragma unroll
            for (int nt = 0; nt < 8; nt++) {
                int coln = warp_n * 64 + nt * 8 + g;
                unsigned b0 = ws[(k0 + c) * WS_STRIDE + coln];
                unsigned b1 = ws[(k0 + c + 4) * WS_STRIDE + coln];
                #pragma unroll
                for (int mt = 0; mt < 2; mt++) {
                    asm volatile(
                        "mma.sync.aligned.m16n8k8.row.col.f32.tf32.tf32.f32 "
                        "{%0,%1,%2,%3}, {%4,%5,%6,%7}, {%8,%9}, {%0,%1,%2,%3};"
                        : "+f"(d[mt][nt][0]), "+f"(d[mt][nt][1]),
                          "+f"(d[mt][nt][2]), "+f"(d[mt][nt][3])
                        : "r"(a[mt][0]), "r"(a[mt][1]), "r"(a[mt][2]), "r"(a[mt][3]),
                          "r"(b0), "r"(b1));
                }
            }
        }
        __syncthreads();
    }

    // ---- epilogue: fp16 feat store + fused el/er ----
    // warp covers cols [warp_n*64, warp_n*64+64) = heads h0 = warp_n*2, h0+1.
    const int h0 = warp_n * 2;
    // attn values for this thread's 8 cols in each head (col = ntl*8 + c*2 + j)
    float al[2][8], ar[2][8];
    #pragma unroll
    for (int q = 0; q < 2; q++)
        #pragma unroll
        for (int i = 0; i < 8; i++) {
            int col = (i >> 1) * 8 + c * 2 + (i & 1);
            al[q][i] = s_attn[(h0 + q) * OUT_CH + col];
            ar[q][i] = s_attn[128 + (h0 + q) * OUT_CH + col];
        }

    #pragma unroll
    for (int mt = 0; mt < 2; mt++) {
        #pragma unroll
        for (int v = 0; v < 2; v++) {          // v=0: frag regs 0,1 ; v=1: regs 2,3 (row+8)
            int row = rbase + warp_m * 32 + mt * 16 + g + v * 8;

            float pl0 = 0.f, pr0 = 0.f, pl1 = 0.f, pr1 = 0.f;
            #pragma unroll
            for (int nt = 0; nt < 4; nt++) {
                float v0 = d[mt][nt][v * 2], v1 = d[mt][nt][v * 2 + 1];
                pl0 += v0 * al[0][nt * 2] + v1 * al[0][nt * 2 + 1];
                pr0 += v0 * ar[0][nt * 2] + v1 * ar[0][nt * 2 + 1];
            }
            #pragma unroll
            for (int nt = 4; nt < 8; nt++) {
                float v0 = d[mt][nt][v * 2], v1 = d[mt][nt][v * 2 + 1];
                pl1 += v0 * al[1][(nt - 4) * 2] + v1 * al[1][(nt - 4) * 2 + 1];
                pr1 += v0 * ar[1][(nt - 4) * 2] + v1 * ar[1][(nt - 4) * 2 + 1];
            }
            // reduce over the 4 lanes of the quad (same row, different cols)
            #pragma unroll
            for (int s = 1; s < 4; s <<= 1) {
                pl0 += __shfl_xor_sync(0xffffffffu, pl0, s, 4);
                pr0 += __shfl_xor_sync(0xffffffffu, pr0, s, 4);
                pl1 += __shfl_xor_sync(0xffffffffu, pl1, s, 4);
                pr1 += __shfl_xor_sync(0xffffffffu, pr1, s, 4);
            }

            if (row < N_NODES) {
                if (c == 0) {
                    g_el[row * HEADS + h0]     = pl0;
                    g_er[row * HEADS + h0]     = pr0;
                    g_el[row * HEADS + h0 + 1] = pl1;
                    g_er[row * HEADS + h0 + 1] = pr1;
                }
                __half* fr = g_feat_h + row * FEAT + warp_n * 64;
                #pragma unroll
                for (int nt = 0; nt < 8; nt++) {
                    __half2 hv = __floats2half2_rn(d[mt][nt][v * 2], d[mt][nt][v * 2 + 1]);
                    *(__half2*)(fr + nt * 8 + c * 2) = hv;
                }
            }
        }
    }
}

// ---------------- 2) CSR build ------------------------------------------------
__global__ void zero_deg_kernel() {
    int i = blockIdx.x * blockDim.x + threadIdx.x;
    if (i < N_PAD) g_deg[i] = 0;
}

__global__ void count_kernel(const int* __restrict__ dst, int nE) {
    int i4 = (blockIdx.x * blockDim.x + threadIdx.x) * 4;
    if (i4 + 3 < nE) {
        int4 d = *(const int4*)(dst + i4);
        atomicAdd(&g_deg[d.x], 1); atomicAdd(&g_deg[d.y], 1);
        atomicAdd(&g_deg[d.z], 1); atomicAdd(&g_deg[d.w], 1);
    } else {
        for (int i = i4; i < nE; i++) atomicAdd(&g_deg[dst[i]], 1);
    }
}

__global__ __launch_bounds__(256) void scan_p1() {
    int t = threadIdx.x, b = blockIdx.x;
    int4 v = *(const int4*)(g_deg + b * 1024 + t * 4);
    int sum = v.x + v.y + v.z + v.w;
    #pragma unroll
    for (int d = 16; d; d >>= 1) sum += __shfl_xor_sync(0xffffffffu, sum, d);
    __shared__ int wsum[8];
    if ((t & 31) == 0) wsum[t >> 5] = sum;
    __syncthreads();
    if (t < 8) {
        int xv = wsum[t];
        #pragma unroll
        for (int d = 4; d; d >>= 1) xv += __shfl_xor_sync(0xffu, xv, d, 8);
        if (t == 0) g_bsum[b] = xv;
    }
}

__global__ __launch_bounds__(256) void scan_p3() {
    int t = threadIdx.x, b = blockIdx.x;
    __shared__ int s_part[2];

    if (t < 64) {
        int v = (t < SCAN_NB && t < b) ? g_bsum[t] : 0;
        #pragma unroll
        for (int d = 16; d; d >>= 1) v += __shfl_xor_sync(0xffffffffu, v, d);
        if ((t & 31) == 0) s_part[t >> 5] = v;
    }
    __syncthreads();
    const int boff = s_part[0] + s_part[1];

    int base = b * 1024 + t * 4;
    int4 v = *(const int4*)(g_deg + base);
    int tsum = v.x + v.y + v.z + v.w;
    int lane = t & 31, wid = t >> 5;
    int inc = tsum;
    #pragma unroll
    for (int d = 1; d < 32; d <<= 1) {
        int u = __shfl_up_sync(0xffffffffu, inc, d);
        if (lane >= d) inc += u;
    }
    __shared__ int wtot[8], woff[8];
    if (lane == 31) wtot[wid] = inc;
    __syncthreads();
    if (t < 8) {
        int xv = wtot[t], p = xv;
        #pragma unroll
        for (int d = 1; d < 8; d <<= 1) {
            int u = __shfl_up_sync(0xffu, p, d, 8);
            if (t >= d) p += u;
        }
        woff[t] = p - xv;
    }
    __syncthreads();
    int pref = boff + woff[wid] + (inc - tsum);
    int4 o;
    o.x = pref;
    o.y = o.x + v.x;
    o.z = o.y + v.y;
    o.w = o.z + v.z;
    *(int4*)(g_off + base) = o;
    *(int4*)(g_cur + base) = o;
}

// ---------------- 3) scatter + edge weights ----------------------------------
__device__ __forceinline__ float lrelu_exp(float e) {
    e = e > 0.f ? e : NEG_SLOPE * e;
    return __expf(e);
}

__global__ void scatter_kernel(const int* __restrict__ src,
                               const int* __restrict__ dst, int nE) {
    int i = blockIdx.x * blockDim.x + threadIdx.x;
    if (i >= nE) return;
    int s = src[i], d = dst[i];
    float4 a = *(const float4*)(g_el + s * 4);
    float4 b = *(const float4*)(g_er + d * 4);
    float4 w;
    w.x = lrelu_exp(a.x + b.x);
    w.y = lrelu_exp(a.y + b.y);
    w.z = lrelu_exp(a.z + b.z);
    w.w = lrelu_exp(a.w + b.w);
    int p = atomicAdd(&g_cur[d], 1);
    g_csr[p] = s;
    *(float4*)(g_w + (size_t)p * 4) = w;
}

// ---------------- 4) aggregation (1 warp / dst node, fp16 gathers) -----------
__global__ __launch_bounds__(256) void aggregate_kernel(const float* __restrict__ bias,
                                                        float* __restrict__ out) {
    int node = (blockIdx.x * blockDim.x + threadIdx.x) >> 5;
    int lane = threadIdx.x & 31;
    if (node >= N_NODES) return;

    int beg = g_off[node], end = g_off[node + 1];
    int hh = lane >> 3;                        // this lane's head

    float4 acc = make_float4(0.f, 0.f, 0.f, 0.f);
    float s = 0.f;
    for (int i = beg; i < end; i++) {
        int sp   = __ldg(&g_csr[i]);                          // uniform
        float wv = __ldg(&g_w[i * 4 + hh]);                   // one sector / warp
        const __half2* fp = (const __half2*)(g_feat_h + sp * FEAT + lane * 4);
        float2 f0 = __half22float2(fp[0]);
        float2 f1 = __half22float2(fp[1]);
        acc.x += wv * f0.x; acc.y += wv * f0.y;
        acc.z += wv * f1.x; acc.w += wv * f1.y;
        s += wv;
    }

    float inv = (end > beg) ? (1.0f / s) : 0.0f;
    float4 bv = *(const float4*)(bias + hh * OUT_CH + (lane & 7) * 4);
    acc.x = acc.x * inv + bv.x;
    acc.y = acc.y * inv + bv.y;
    acc.z = acc.z * inv + bv.z;
    acc.w = acc.w * inv + bv.w;

    #pragma unroll
    for (int d = 8; d < 32; d <<= 1) {
        acc.x += __shfl_xor_sync(0xffffffffu, acc.x, d);
        acc.y += __shfl_xor_sync(0xffffffffu, acc.y, d);
        acc.z += __shfl_xor_sync(0xffffffffu, acc.z, d);
        acc.w += __shfl_xor_sync(0xffffffffu, acc.w, d);
    }
    if (lane < 8) {
        acc.x *= 0.25f; acc.y *= 0.25f; acc.z *= 0.25f; acc.w *= 0.25f;
        *(float4*)(out + node * OUT_CH + lane * 4) = acc;
    }
}

// ---------------- launch ------------------------------------------------------
extern "C" void kernel_launch(void* const* d_in, const int* in_sizes, int n_in,
                              void* d_out, int out_size) {
    const float* x      = (const float*)d_in[0];
    const int*   src    = (const int*)  d_in[1];
    const int*   dst    = (const int*)  d_in[2];
    const float* W      = (const float*)d_in[3];
    const float* attn_l = (const float*)d_in[4];
    const float* attn_r = (const float*)d_in[5];
    const float* bias   = (const float*)d_in[6];
    float*       out    = (float*)d_out;

    const int nE = in_sizes[1];

    // CSR build
    zero_deg_kernel<<<(N_PAD + 255) / 256, 256>>>();
    count_kernel<<<((nE + 3) / 4 + 255) / 256, 256>>>(dst, nE);
    scan_p1<<<SCAN_NB, 256>>>();
    scan_p3<<<SCAN_NB, 256>>>();

    // tf32 tensor-core projection + fused attention terms + fp16 feature store
    gemm_kernel<<<(N_NODES + 127) / 128, 256>>>(x, W, attn_l, attn_r);

    // edge weights + CSR scatter
    scatter_kernel<<<(nE + 255) / 256, 256>>>(src, dst, nE);

    // fused softmax-normalize + aggregate + head mean
    aggregate_kernel<<<(N_NODES * 32 + 255) / 256, 256>>>(bias, out);
}

// round 5
// speedup vs baseline: 5.4939x; 1.1584x over previous
#include <cuda_runtime.h>
#include <cuda_fp16.h>

#define N_NODES 50000
#define N_PAD   50176            // 49 * 1024
#define IN_CH   128
#define HEADS   4
#define OUT_CH  32
#define FEAT    128
#define NEG_SLOPE 0.2f
#define SCAN_NB 49
#define MAX_E   800000

// ---------------- scratch (static device globals: allocation-free) -----------
__device__ __align__(16) __half g_feat_h[N_NODES * FEAT];  // fp16 features [n][h*32+d]
__device__ __align__(16) float  g_el[N_NODES * HEADS];
__device__ __align__(16) float  g_er[N_NODES * HEADS];
__device__ __align__(16) int    g_deg[N_PAD];
__device__ __align__(16) int    g_off[N_PAD + 16];
__device__ __align__(16) int    g_cur[N_PAD];
__device__ int g_bsum[SCAN_NB];
__device__ __align__(16) int    g_csr[MAX_E];
__device__ __align__(16) float  g_w[MAX_E * 4];            // per-edge per-head exp weights

// ---------------- side stream + events for forked capture --------------------
static cudaStream_t g_s2;
static cudaEvent_t  g_ev_fork, g_ev_join;
static struct StreamInit {
    StreamInit() {
        cudaStreamCreateWithFlags(&g_s2, cudaStreamNonBlocking);
        cudaEventCreateWithFlags(&g_ev_fork, cudaEventDisableTiming);
        cudaEventCreateWithFlags(&g_ev_join, cudaEventDisableTiming);
    }
} g_stream_init;

__device__ __forceinline__ unsigned f2tf32(float f) {
    unsigned o;
    asm("cvt.rna.tf32.f32 %0, %1;" : "=r"(o) : "f"(f));
    return o;
}

// ---------------- 1) feat = x @ W via tf32 mma + fused el/er epilogue --------
#define XS_STRIDE 36
#define WS_STRIDE 136

__global__ __launch_bounds__(256) void gemm_kernel(const float* __restrict__ x,
                                                   const float* __restrict__ W,
                                                   const float* __restrict__ attn_l,
                                                   const float* __restrict__ attn_r) {
    __shared__ unsigned xs[128 * XS_STRIDE];
    __shared__ unsigned ws[32 * WS_STRIDE];
    __shared__ float    s_attn[256];

    const int t      = threadIdx.x;
    const int lane   = t & 31;
    const int wid    = t >> 5;
    const int warp_m = wid & 3;
    const int warp_n = wid >> 2;
    const int g      = lane >> 2;
    const int c      = lane & 3;
    const int rbase  = blockIdx.x * 128;

    s_attn[t] = (t < 128) ? attn_l[t] : attn_r[t - 128];

    float d[2][8][4];
    #pragma unroll
    for (int mt = 0; mt < 2; mt++)
        #pragma unroll
        for (int nt = 0; nt < 8; nt++)
            #pragma unroll
            for (int q = 0; q < 4; q++) d[mt][nt][q] = 0.f;

    for (int kk = 0; kk < IN_CH; kk += 32) {
        #pragma unroll
        for (int p = 0; p < 4; p++) {
            int idx = p * 256 + t;
            int r = idx >> 3, c4 = idx & 7;
            int row = rbase + r;
            float4 xv = make_float4(0.f, 0.f, 0.f, 0.f);
            if (row < N_NODES) xv = *(const float4*)(x + row * IN_CH + kk + c4 * 4);
            unsigned* dptr = xs + r * XS_STRIDE + c4 * 4;
            dptr[0] = f2tf32(xv.x); dptr[1] = f2tf32(xv.y);
            dptr[2] = f2tf32(xv.z); dptr[3] = f2tf32(xv.w);
        }
        #pragma unroll
        for (int p = 0; p < 4; p++) {
            int idx = p * 256 + t;
            int k = idx >> 5, n4 = idx & 31;
            float4 wv = *(const float4*)(W + (kk + k) * FEAT + n4 * 4);
            unsigned* dptr = ws + k * WS_STRIDE + n4 * 4;
            dptr[0] = f2tf32(wv.x); dptr[1] = f2tf32(wv.y);
            dptr[2] = f2tf32(wv.z); dptr[3] = f2tf32(wv.w);
        }
        __syncthreads();

        #pragma unroll
        for (int k0 = 0; k0 < 32; k0 += 8) {
            unsigned a[2][4];
            #pragma unroll
            for (int mt = 0; mt < 2; mt++) {
                int r0 = (warp_m * 32 + mt * 16 + g) * XS_STRIDE + k0 + c;
                int r1 = r0 + 8 * XS_STRIDE;
                a[mt][0] = xs[r0];     a[mt][1] = xs[r1];
                a[mt][2] = xs[r0 + 4]; a[mt][3] = xs[r1 + 4];
            }
            #pragma unroll
            for (int nt = 0; nt < 8; nt++) {
                int coln = warp_n * 64 + nt * 8 + g;
                unsigned b0 = ws[(k0 + c) * WS_STRIDE + coln];
                unsigned b1 = ws[(k0 + c + 4) * WS_STRIDE + coln];
                #pragma unroll
                for (int mt = 0; mt < 2; mt++) {
                    asm volatile(
                        "mma.sync.aligned.m16n8k8.row.col.f32.tf32.tf32.f32 "
                        "{%0,%1,%2,%3}, {%4,%5,%6,%7}, {%8,%9}, {%0,%1,%2,%3};"
                        : "+f"(d[mt][nt][0]), "+f"(d[mt][nt][1]),
                          "+f"(d[mt][nt][2]), "+f"(d[mt][nt][3])
                        : "r"(a[mt][0]), "r"(a[mt][1]), "r"(a[mt][2]), "r"(a[mt][3]),
                          "r"(b0), "r"(b1));
                }
            }
        }
        __syncthreads();
    }

    const int h0 = warp_n * 2;
    float al[2][8], ar[2][8];
    #pragma unroll
    for (int q = 0; q < 2; q++)
        #pragma unroll
        for (int i = 0; i < 8; i++) {
            int col = (i >> 1) * 8 + c * 2 + (i & 1);
            al[q][i] = s_attn[(h0 + q) * OUT_CH + col];
            ar[q][i] = s_attn[128 + (h0 + q) * OUT_CH + col];
        }

    #pragma unroll
    for (int mt = 0; mt < 2; mt++) {
        #pragma unroll
        for (int v = 0; v < 2; v++) {
            int row = rbase + warp_m * 32 + mt * 16 + g + v * 8;

            float pl0 = 0.f, pr0 = 0.f, pl1 = 0.f, pr1 = 0.f;
            #pragma unroll
            for (int nt = 0; nt < 4; nt++) {
                float v0 = d[mt][nt][v * 2], v1 = d[mt][nt][v * 2 + 1];
                pl0 += v0 * al[0][nt * 2] + v1 * al[0][nt * 2 + 1];
                pr0 += v0 * ar[0][nt * 2] + v1 * ar[0][nt * 2 + 1];
            }
            #pragma unroll
            for (int nt = 4; nt < 8; nt++) {
                float v0 = d[mt][nt][v * 2], v1 = d[mt][nt][v * 2 + 1];
                pl1 += v0 * al[1][(nt - 4) * 2] + v1 * al[1][(nt - 4) * 2 + 1];
                pr1 += v0 * ar[1][(nt - 4) * 2] + v1 * ar[1][(nt - 4) * 2 + 1];
            }
            #pragma unroll
            for (int s = 1; s < 4; s <<= 1) {
                pl0 += __shfl_xor_sync(0xffffffffu, pl0, s, 4);
                pr0 += __shfl_xor_sync(0xffffffffu, pr0, s, 4);
                pl1 += __shfl_xor_sync(0xffffffffu, pl1, s, 4);
                pr1 += __shfl_xor_sync(0xffffffffu, pr1, s, 4);
            }

            if (row < N_NODES) {
                if (c == 0) {
                    g_el[row * HEADS + h0]     = pl0;
                    g_er[row * HEADS + h0]     = pr0;
                    g_el[row * HEADS + h0 + 1] = pl1;
                    g_er[row * HEADS + h0 + 1] = pr1;
                }
                __half* fr = g_feat_h + row * FEAT + warp_n * 64;
                #pragma unroll
                for (int nt = 0; nt < 8; nt++) {
                    __half2 hv = __floats2half2_rn(d[mt][nt][v * 2], d[mt][nt][v * 2 + 1]);
                    *(__half2*)(fr + nt * 8 + c * 2) = hv;
                }
            }
        }
    }
}

// ---------------- 2) CSR build ------------------------------------------------
__global__ void count_kernel(const int* __restrict__ dst, int nE) {
    int i4 = (blockIdx.x * blockDim.x + threadIdx.x) * 4;
    if (i4 + 3 < nE) {
        int4 d = *(const int4*)(dst + i4);
        atomicAdd(&g_deg[d.x], 1); atomicAdd(&g_deg[d.y], 1);
        atomicAdd(&g_deg[d.z], 1); atomicAdd(&g_deg[d.w], 1);
    } else {
        for (int i = i4; i < nE; i++) atomicAdd(&g_deg[dst[i]], 1);
    }
}

__global__ __launch_bounds__(256) void scan_p1() {
    int t = threadIdx.x, b = blockIdx.x;
    int4 v = *(const int4*)(g_deg + b * 1024 + t * 4);
    int sum = v.x + v.y + v.z + v.w;
    #pragma unroll
    for (int d = 16; d; d >>= 1) sum += __shfl_xor_sync(0xffffffffu, sum, d);
    __shared__ int wsum[8];
    if ((t & 31) == 0) wsum[t >> 5] = sum;
    __syncthreads();
    if (t < 8) {
        int xv = wsum[t];
        #pragma unroll
        for (int d = 4; d; d >>= 1) xv += __shfl_xor_sync(0xffu, xv, d, 8);
        if (t == 0) g_bsum[b] = xv;
    }
}

__global__ __launch_bounds__(256) void scan_p3() {
    int t = threadIdx.x, b = blockIdx.x;
    __shared__ int s_part[2];

    if (t < 64) {
        int v = (t < SCAN_NB && t < b) ? g_bsum[t] : 0;
        #pragma unroll
        for (int d = 16; d; d >>= 1) v += __shfl_xor_sync(0xffffffffu, v, d);
        if ((t & 31) == 0) s_part[t >> 5] = v;
    }
    __syncthreads();
    const int boff = s_part[0] + s_part[1];

    int base = b * 1024 + t * 4;
    int4 v = *(const int4*)(g_deg + base);
    int tsum = v.x + v.y + v.z + v.w;
    int lane = t & 31, wid = t >> 5;
    int inc = tsum;
    #pragma unroll
    for (int d = 1; d < 32; d <<= 1) {
        int u = __shfl_up_sync(0xffffffffu, inc, d);
        if (lane >= d) inc += u;
    }
    __shared__ int wtot[8], woff[8];
    if (lane == 31) wtot[wid] = inc;
    __syncthreads();
    if (t < 8) {
        int xv = wtot[t], p = xv;
        #pragma unroll
        for (int d = 1; d < 8; d <<= 1) {
            int u = __shfl_up_sync(0xffu, p, d, 8);
            if (t >= d) p += u;
        }
        woff[t] = p - xv;
    }
    __syncthreads();
    int pref = boff + woff[wid] + (inc - tsum);
    int4 o;
    o.x = pref;
    o.y = o.x + v.x;
    o.z = o.y + v.y;
    o.w = o.z + v.z;
    *(int4*)(g_off + base) = o;
    *(int4*)(g_cur + base) = o;
}

// ---------------- 3) scatter + edge weights ----------------------------------
__device__ __forceinline__ float lrelu_exp(float e) {
    e = e > 0.f ? e : NEG_SLOPE * e;
    return __expf(e);
}

__global__ void scatter_kernel(const int* __restrict__ src,
                               const int* __restrict__ dst, int nE) {
    int i = blockIdx.x * blockDim.x + threadIdx.x;
    if (i >= nE) return;
    int s = src[i], d = dst[i];
    float4 a = *(const float4*)(g_el + s * 4);
    float4 b = *(const float4*)(g_er + d * 4);
    float4 w;
    w.x = lrelu_exp(a.x + b.x);
    w.y = lrelu_exp(a.y + b.y);
    w.z = lrelu_exp(a.z + b.z);
    w.w = lrelu_exp(a.w + b.w);
    int p = atomicAdd(&g_cur[d], 1);
    g_csr[p] = s;
    *(float4*)(g_w + (size_t)p * 4) = w;
}

// ---------------- 4) aggregation (half-warp per node, float4 fp16 gathers) ---
__global__ __launch_bounds__(256) void aggregate_kernel(const float* __restrict__ bias,
                                                        float* __restrict__ out) {
    int node = (blockIdx.x * blockDim.x + threadIdx.x) >> 4;
    int l    = threadIdx.x & 15;               // lane within half-warp
    if (node >= N_NODES) return;

    int beg = g_off[node], end = g_off[node + 1];
    int hh = l >> 2;                           // this lane's head (8 dims of it)

    float acc[8];
    #pragma unroll
    for (int j = 0; j < 8; j++) acc[j] = 0.f;
    float s = 0.f;

    for (int i = beg; i < end; i++) {
        int sp   = __ldg(&g_csr[i]);
        float wv = __ldg(&g_w[i * 4 + hh]);
        float4 raw = *(const float4*)(g_feat_h + (size_t)sp * FEAT + l * 8);
        const __half2* hp = (const __half2*)&raw;
        #pragma unroll
        for (int q = 0; q < 4; q++) {
            float2 f = __half22float2(hp[q]);
            acc[2 * q]     += wv * f.x;
            acc[2 * q + 1] += wv * f.y;
        }
        s += wv;
    }

    float inv = (end > beg) ? (1.0f / s) : 0.0f;
    const float* bp = bias + hh * OUT_CH + (l & 3) * 8;
    #pragma unroll
    for (int j = 0; j < 8; j++) acc[j] = acc[j] * inv + bp[j];

    // sum over heads: lanes l, l^4, l^8, l^12 hold the same output dims
    #pragma unroll
    for (int d = 4; d < 16; d <<= 1)
        #pragma unroll
        for (int j = 0; j < 8; j++)
            acc[j] += __shfl_xor_sync(0xffffffffu, acc[j], d, 16);

    if (l < 4) {
        float4 o0 = make_float4(acc[0] * 0.25f, acc[1] * 0.25f,
                                acc[2] * 0.25f, acc[3] * 0.25f);
        float4 o1 = make_float4(acc[4] * 0.25f, acc[5] * 0.25f,
                                acc[6] * 0.25f, acc[7] * 0.25f);
        *(float4*)(out + node * OUT_CH + l * 8)     = o0;
        *(float4*)(out + node * OUT_CH + l * 8 + 4) = o1;
    }
}

// ---------------- launch ------------------------------------------------------
extern "C" void kernel_launch(void* const* d_in, const int* in_sizes, int n_in,
                              void* d_out, int out_size) {
    const float* x      = (const float*)d_in[0];
    const int*   src    = (const int*)  d_in[1];
    const int*   dst    = (const int*)  d_in[2];
    const float* W      = (const float*)d_in[3];
    const float* attn_l = (const float*)d_in[4];
    const float* attn_r = (const float*)d_in[5];
    const float* bias   = (const float*)d_in[6];
    float*       out    = (float*)d_out;

    const int nE = in_sizes[1];

    // fork: gemm runs on side stream, concurrent with CSR build
    cudaEventRecord(g_ev_fork, 0);
    cudaStreamWaitEvent(g_s2, g_ev_fork, 0);
    gemm_kernel<<<(N_NODES + 127) / 128, 256, 0, g_s2>>>(x, W, attn_l, attn_r);
    cudaEventRecord(g_ev_join, g_s2);

    // CSR build on main stream
    void* deg_ptr = nullptr;
    cudaGetSymbolAddress(&deg_ptr, g_deg);
    cudaMemsetAsync(deg_ptr, 0, N_PAD * sizeof(int), 0);
    count_kernel<<<((nE + 3) / 4 + 255) / 256, 256>>>(dst, nE);
    scan_p1<<<SCAN_NB, 256>>>();
    scan_p3<<<SCAN_NB, 256>>>();

    // join: scatter needs both el/er (gemm) and g_cur (scan)
    cudaStreamWaitEvent(0, g_ev_join, 0);
    scatter_kernel<<<(nE + 255) / 256, 256>>>(src, dst, nE);

    // fused softmax-normalize + aggregate + head mean
    aggregate_kernel<<<(N_NODES * 16 + 255) / 256, 256>>>(bias, out);
}

// round 6
// speedup vs baseline: 5.9606x; 1.0850x over previous
#include <cuda_runtime.h>
#include <cuda_fp16.h>

#define N_NODES 50000
#define N_PAD   50176            // 49 * 1024
#define IN_CH   128
#define HEADS   4
#define OUT_CH  32
#define FEAT    128
#define NEG_SLOPE 0.2f
#define SCAN_NB 49
#define MAX_E   800000

// ---------------- scratch (static device globals: allocation-free) -----------
__device__ __align__(16) __half g_feat_h[N_NODES * FEAT];  // fp16 features [n][h*32+d]
__device__ __align__(16) float  g_el[N_NODES * HEADS];
__device__ __align__(16) float  g_er[N_NODES * HEADS];
// g_deg[N_PAD] = degree counters; g_deg[N_PAD] (one past) = scan arrival counter.
// The memset covers N_PAD+4 ints so the barrier resets on every graph replay.
__device__ __align__(16) int    g_deg[N_PAD + 4];
__device__ __align__(16) int    g_off[N_PAD + 16];
__device__ __align__(16) int    g_cur[N_PAD];
__device__ volatile int g_bsum[SCAN_NB];
__device__ __align__(16) int    g_csr[MAX_E];

// ---------------- side stream + events for forked capture --------------------
static cudaStream_t g_s2;
static cudaEvent_t  g_ev_fork, g_ev_join;
static struct StreamInit {
    StreamInit() {
        cudaStreamCreateWithFlags(&g_s2, cudaStreamNonBlocking);
        cudaEventCreateWithFlags(&g_ev_fork, cudaEventDisableTiming);
        cudaEventCreateWithFlags(&g_ev_join, cudaEventDisableTiming);
    }
} g_stream_init;

__device__ __forceinline__ unsigned f2tf32(float f) {
    unsigned o;
    asm("cvt.rna.tf32.f32 %0, %1;" : "=r"(o) : "f"(f));
    return o;
}

// ---------------- 1) feat = x @ W via tf32 mma + fused el/er epilogue --------
#define XS_STRIDE 36
#define WS_STRIDE 136

__global__ __launch_bounds__(256) void gemm_kernel(const float* __restrict__ x,
                                                   const float* __restrict__ W,
                                                   const float* __restrict__ attn_l,
                                                   const float* __restrict__ attn_r) {
    __shared__ unsigned xs[128 * XS_STRIDE];
    __shared__ unsigned ws[32 * WS_STRIDE];
    __shared__ float    s_attn[256];

    const int t      = threadIdx.x;
    const int lane   = t & 31;
    const int wid    = t >> 5;
    const int warp_m = wid & 3;
    const int warp_n = wid >> 2;
    const int g      = lane >> 2;
    const int c      = lane & 3;
    const int rbase  = blockIdx.x * 128;

    s_attn[t] = (t < 128) ? attn_l[t] : attn_r[t - 128];

    float d[2][8][4];
    #pragma unroll
    for (int mt = 0; mt < 2; mt++)
        #pragma unroll
        for (int nt = 0; nt < 8; nt++)
            #pragma unroll
            for (int q = 0; q < 4; q++) d[mt][nt][q] = 0.f;

    for (int kk = 0; kk < IN_CH; kk += 32) {
        #pragma unroll
        for (int p = 0; p < 4; p++) {
            int idx = p * 256 + t;
            int r = idx >> 3, c4 = idx & 7;
            int row = rbase + r;
            float4 xv = make_float4(0.f, 0.f, 0.f, 0.f);
            if (row < N_NODES) xv = *(const float4*)(x + row * IN_CH + kk + c4 * 4);
            unsigned* dptr = xs + r * XS_STRIDE + c4 * 4;
            dptr[0] = f2tf32(xv.x); dptr[1] = f2tf32(xv.y);
            dptr[2] = f2tf32(xv.z); dptr[3] = f2tf32(xv.w);
        }
        #pragma unroll
        for (int p = 0; p < 4; p++) {
            int idx = p * 256 + t;
            int k = idx >> 5, n4 = idx & 31;
            float4 wv = *(const float4*)(W + (kk + k) * FEAT + n4 * 4);
            unsigned* dptr = ws + k * WS_STRIDE + n4 * 4;
            dptr[0] = f2tf32(wv.x); dptr[1] = f2tf32(wv.y);
            dptr[2] = f2tf32(wv.z); dptr[3] = f2tf32(wv.w);
        }
        __syncthreads();

        #pragma unroll
        for (int k0 = 0; k0 < 32; k0 += 8) {
            unsigned a[2][4];
            #pragma unroll
            for (int mt = 0; mt < 2; mt++) {
                int r0 = (warp_m * 32 + mt * 16 + g) * XS_STRIDE + k0 + c;
                int r1 = r0 + 8 * XS_STRIDE;
                a[mt][0] = xs[r0];     a[mt][1] = xs[r1];
                a[mt][2] = xs[r0 + 4]; a[mt][3] = xs[r1 + 4];
            }
            #pragma unroll
            for (int nt = 0; nt < 8; nt++) {
                int coln = warp_n * 64 + nt * 8 + g;
                unsigned b0 = ws[(k0 + c) * WS_STRIDE + coln];
                unsigned b1 = ws[(k0 + c + 4) * WS_STRIDE + coln];
                #pragma unroll
                for (int mt = 0; mt < 2; mt++) {
                    asm volatile(
                        "mma.sync.aligned.m16n8k8.row.col.f32.tf32.tf32.f32 "
                        "{%0,%1,%2,%3}, {%4,%5,%6,%7}, {%8,%9}, {%0,%1,%2,%3};"
                        : "+f"(d[mt][nt][0]), "+f"(d[mt][nt][1]),
                          "+f"(d[mt][nt][2]), "+f"(d[mt][nt][3])
                        : "r"(a[mt][0]), "r"(a[mt][1]), "r"(a[mt][2]), "r"(a[mt][3]),
                          "r"(b0), "r"(b1));
                }
            }
        }
        __syncthreads();
    }

    const int h0 = warp_n * 2;
    float al[2][8], ar[2][8];
    #pragma unroll
    for (int q = 0; q < 2; q++)
        #pragma unroll
        for (int i = 0; i < 8; i++) {
            int col = (i >> 1) * 8 + c * 2 + (i & 1);
            al[q][i] = s_attn[(h0 + q) * OUT_CH + col];
            ar[q][i] = s_attn[128 + (h0 + q) * OUT_CH + col];
        }

    #pragma unroll
    for (int mt = 0; mt < 2; mt++) {
        #pragma unroll
        for (int v = 0; v < 2; v++) {
            int row = rbase + warp_m * 32 + mt * 16 + g + v * 8;

            float pl0 = 0.f, pr0 = 0.f, pl1 = 0.f, pr1 = 0.f;
            #pragma unroll
            for (int nt = 0; nt < 4; nt++) {
                float v0 = d[mt][nt][v * 2], v1 = d[mt][nt][v * 2 + 1];
                pl0 += v0 * al[0][nt * 2] + v1 * al[0][nt * 2 + 1];
                pr0 += v0 * ar[0][nt * 2] + v1 * ar[0][nt * 2 + 1];
            }
            #pragma unroll
            for (int nt = 4; nt < 8; nt++) {
                float v0 = d[mt][nt][v * 2], v1 = d[mt][nt][v * 2 + 1];
                pl1 += v0 * al[1][(nt - 4) * 2] + v1 * al[1][(nt - 4) * 2 + 1];
                pr1 += v0 * ar[1][(nt - 4) * 2] + v1 * ar[1][(nt - 4) * 2 + 1];
            }
            #pragma unroll
            for (int s = 1; s < 4; s <<= 1) {
                pl0 += __shfl_xor_sync(0xffffffffu, pl0, s, 4);
                pr0 += __shfl_xor_sync(0xffffffffu, pr0, s, 4);
                pl1 += __shfl_xor_sync(0xffffffffu, pl1, s, 4);
                pr1 += __shfl_xor_sync(0xffffffffu, pr1, s, 4);
            }

            if (row < N_NODES) {
                if (c == 0) {
                    g_el[row * HEADS + h0]     = pl0;
                    g_er[row * HEADS + h0]     = pr0;
                    g_el[row * HEADS + h0 + 1] = pl1;
                    g_er[row * HEADS + h0 + 1] = pr1;
                }
                __half* fr = g_feat_h + row * FEAT + warp_n * 64;
                #pragma unroll
                for (int nt = 0; nt < 8; nt++) {
                    __half2 hv = __floats2half2_rn(d[mt][nt][v * 2], d[mt][nt][v * 2 + 1]);
                    *(__half2*)(fr + nt * 8 + c * 2) = hv;
                }
            }
        }
    }
}

// ---------------- 2) CSR build ------------------------------------------------
__global__ void count_kernel(const int* __restrict__ dst, int nE) {
    int i4 = (blockIdx.x * blockDim.x + threadIdx.x) * 4;
    if (i4 + 3 < nE) {
        int4 d = *(const int4*)(dst + i4);
        atomicAdd(&g_deg[d.x], 1); atomicAdd(&g_deg[d.y], 1);
        atomicAdd(&g_deg[d.z], 1); atomicAdd(&g_deg[d.w], 1);
    } else {
        for (int i = i4; i < nE; i++) atomicAdd(&g_deg[dst[i]], 1);
    }
}

// fused exclusive scan: one launch, grid-wide spin barrier (49 blocks, all resident)
__global__ __launch_bounds__(256) void scan_fused() {
    int t = threadIdx.x, b = blockIdx.x;
    int base = b * 1024 + t * 4;
    int4 v = *(const int4*)(g_deg + base);
    int tsum = v.x + v.y + v.z + v.w;
    int lane = t & 31, wid = t >> 5;

    // intra-block inclusive scan of per-thread sums
    int inc = tsum;
    #pragma unroll
    for (int d = 1; d < 32; d <<= 1) {
        int u = __shfl_up_sync(0xffffffffu, inc, d);
        if (lane >= d) inc += u;
    }
    __shared__ int wtot[8], woff[8], s_total;
    if (lane == 31) wtot[wid] = inc;
    __syncthreads();
    if (t < 8) {
        int xv = wtot[t], p = xv;
        #pragma unroll
        for (int d = 1; d < 8; d <<= 1) {
            int u = __shfl_up_sync(0xffu, p, d, 8);
            if (t >= d) p += u;
        }
        woff[t] = p - xv;
        if (t == 7) s_total = p;
    }
    __syncthreads();

    // publish block total, arrive at grid barrier, spin
    if (t == 0) {
        g_bsum[b] = s_total;
        __threadfence();
        atomicAdd(&g_deg[N_PAD], 1);
        while (((volatile int*)g_deg)[N_PAD] < SCAN_NB) { }
        __threadfence();
    }
    __syncthreads();

    // exclusive prefix over preceding blocks
    __shared__ int s_part[2];
    if (t < 64) {
        int pv = (t < SCAN_NB && t < b) ? g_bsum[t] : 0;
        #pragma unroll
        for (int d = 16; d; d >>= 1) pv += __shfl_xor_sync(0xffffffffu, pv, d);
        if ((t & 31) == 0) s_part[t >> 5] = pv;
    }
    __syncthreads();
    const int boff = s_part[0] + s_part[1];

    int pref = boff + woff[wid] + (inc - tsum);
    int4 o;
    o.x = pref;
    o.y = o.x + v.x;
    o.z = o.y + v.y;
    o.w = o.z + v.z;
    *(int4*)(g_off + base) = o;
    *(int4*)(g_cur + base) = o;
}

// ---------------- 3) scatter (csr only — weights computed in aggregate) ------
__global__ void scatter_kernel(const int* __restrict__ src,
                               const int* __restrict__ dst, int nE) {
    int i = blockIdx.x * blockDim.x + threadIdx.x;
    if (i >= nE) return;
    int p = atomicAdd(&g_cur[dst[i]], 1);
    g_csr[p] = src[i];
}

// ---------------- 4) aggregation (half-warp per node, inline edge weights) ---
__global__ __launch_bounds__(256) void aggregate_kernel(const float* __restrict__ bias,
                                                        float* __restrict__ out) {
    int node = (blockIdx.x * blockDim.x + threadIdx.x) >> 4;
    int l    = threadIdx.x & 15;               // lane within half-warp
    if (node >= N_NODES) return;

    int beg = g_off[node], end = g_off[node + 1];
    int hh = l >> 2;                           // this lane's head (8 dims of it)

    const float er_h = __ldg(&g_er[node * HEADS + hh]);   // uniform per node

    float acc[8];
    #pragma unroll
    for (int j = 0; j < 8; j++) acc[j] = 0.f;
    float s = 0.f;

    for (int i = beg; i < end; i++) {
        int sp = __ldg(&g_csr[i]);
        float e = __ldg(&g_el[sp * HEADS + hh]) + er_h;    // 1 sector / half-warp
        e = e > 0.f ? e : NEG_SLOPE * e;
        float wv = __expf(e);
        float4 raw = *(const float4*)(g_feat_h + (size_t)sp * FEAT + l * 8);
        const __half2* hp = (const __half2*)&raw;
        #pragma unroll
        for (int q = 0; q < 4; q++) {
            float2 f = __half22float2(hp[q]);
            acc[2 * q]     += wv * f.x;
            acc[2 * q + 1] += wv * f.y;
        }
        s += wv;
    }

    float inv = (end > beg) ? (1.0f / s) : 0.0f;
    const float* bp = bias + hh * OUT_CH + (l & 3) * 8;
    #pragma unroll
    for (int j = 0; j < 8; j++) acc[j] = acc[j] * inv + bp[j];

    // sum over heads: lanes l, l^4, l^8, l^12 hold the same output dims
    #pragma unroll
    for (int d = 4; d < 16; d <<= 1)
        #pragma unroll
        for (int j = 0; j < 8; j++)
            acc[j] += __shfl_xor_sync(0xffffffffu, acc[j], d, 16);

    if (l < 4) {
        float4 o0 = make_float4(acc[0] * 0.25f, acc[1] * 0.25f,
                                acc[2] * 0.25f, acc[3] * 0.25f);
        float4 o1 = make_float4(acc[4] * 0.25f, acc[5] * 0.25f,
                                acc[6] * 0.25f, acc[7] * 0.25f);
        *(float4*)(out + node * OUT_CH + l * 8)     = o0;
        *(float4*)(out + node * OUT_CH + l * 8 + 4) = o1;
    }
}

// ---------------- launch ------------------------------------------------------
extern "C" void kernel_launch(void* const* d_in, const int* in_sizes, int n_in,
                              void* d_out, int out_size) {
    const float* x      = (const float*)d_in[0];
    const int*   src    = (const int*)  d_in[1];
    const int*   dst    = (const int*)  d_in[2];
    const float* W      = (const float*)d_in[3];
    const float* attn_l = (const float*)d_in[4];
    const float* attn_r = (const float*)d_in[5];
    const float* bias   = (const float*)d_in[6];
    float*       out    = (float*)d_out;

    const int nE = in_sizes[1];

    // fork: gemm runs on side stream, concurrent with CSR build
    cudaEventRecord(g_ev_fork, 0);
    cudaStreamWaitEvent(g_s2, g_ev_fork, 0);
    gemm_kernel<<<(N_NODES + 127) / 128, 256, 0, g_s2>>>(x, W, attn_l, attn_r);
    cudaEventRecord(g_ev_join, g_s2);

    // CSR build on main stream (memset also resets the scan's arrival counter)
    void* deg_ptr = nullptr;
    cudaGetSymbolAddress(&deg_ptr, g_deg);
    cudaMemsetAsync(deg_ptr, 0, (N_PAD + 4) * sizeof(int), 0);
    count_kernel<<<((nE + 3) / 4 + 255) / 256, 256>>>(dst, nE);
    scan_fused<<<SCAN_NB, 256>>>();
    scatter_kernel<<<(nE + 255) / 256, 256>>>(src, dst, nE);

    // join: aggregate needs feat/el/er (gemm) and csr (scatter)
    cudaStreamWaitEvent(0, g_ev_join, 0);
    aggregate_kernel<<<(N_NODES * 16 + 255) / 256, 256>>>(bias, out);
}